// round 15
// baseline (speedup 1.0000x reference)
#include <cuda_runtime.h>

// CGMMTransition: N=10000, L=5, A=6, C=20, C2=20
// R13 structure (third-n blocks, grid 30000) with PHASE-SPLIT stores:
// phase A writes the tile's rightmost_term contiguously, phase B recomputes
// (T is L1-resident) and writes transition_posterior contiguously, halving
// the number of interleaved DRAM write streams per warp.
// Outputs (concatenated in d_out, fp32):
//   p_Q_given_obs        [N, C]           at offset 0
//   transition_posterior [N, L, A, C, C2] at offset N*C
//   rightmost_term       [N, L, A, C, C2] at offset N*C + N*L*A*C*C2

#define LVAL   5
#define AVAL   6
#define CVAL   20
#define C2VAL  20
#define LA     30      // L*A
#define LAT    10      // la rows per tile (third of an n)
#define KDIM   600     // LA*C2
#define KDIMT  200     // stats floats per tile
#define PER_N  12000   // LA*C*C2
#define PER_T4 1000    // float4s per tile
#define NTHREADS 256
#define NWARPS 8
#define NITER  4       // ceil(1000/256); iter 3 partial (tid < 232)
#define TAIL   (PER_T4 - 3 * NTHREADS)    // 232

__global__ void zero_pq_kernel(float* __restrict__ out_pq, int total)
{
    int i = blockIdx.x * blockDim.x + threadIdx.x;
    if (i < total) out_pq[i] = 0.0f;
}

__global__ void __launch_bounds__(NTHREADS, 8)
cgmm_kernel(const float* __restrict__ stats,
            const float* __restrict__ layerS,
            const float* __restrict__ arcS,
            const float* __restrict__ T,
            float* __restrict__ out_pq,
            float* __restrict__ out_tp,
            float* __restrict__ out_rt)
{
    __shared__ float s_stats[KDIMT];          // this tile's 10 rows
    __shared__ float s_inv[LAT];
    __shared__ float s_w[LAT];
    __shared__ float s_pqw[NWARPS][CVAL];     // per-warp c-bins (non-atomic)

    const int tid  = threadIdx.x;
    const int warp = tid >> 5;
    const int lane = tid & 31;

    const int n   = blockIdx.x / 3;
    const int t3  = blockIdx.x - 3 * n;        // tile index 0..2
    const int la0 = t3 * LAT;                  // global la base for this tile

    // ---- Phase 0: stage this tile's stats (50 float4s; guard < 256 OK) ----
    const float4* g_stats4 = reinterpret_cast<const float4*>(
        stats + (size_t)n * KDIM + la0 * C2VAL);   // byte off 800*t3: aligned
    if (tid < KDIMT / 4) {
        float4 v = __ldcs(&g_stats4[tid]);    // streamed: read exactly once
        reinterpret_cast<float4*>(s_stats)[tid] = v;
    }
    if (tid < NWARPS * CVAL)                   // 160 < 256 OK
        reinterpret_cast<float*>(s_pqw)[tid] = 0.0f;
    if (tid < LAT)                             // 10 < 256 OK
        s_w[tid] = layerS[(la0 + tid) / AVAL] * arcS[la0 + tid];
    __syncthreads();

    // ---- Phase 1: inverse row-sums (10 rows; guard < 256 OK) ----
    if (tid < LAT) {
        float s = 0.0f;
        #pragma unroll
        for (int j = 0; j < C2VAL; ++j) s += s_stats[tid * C2VAL + j];
        s_inv[tid] = (s == 0.0f) ? 1.0f : 1.0f / s;
    }
    __syncthreads();

    const size_t base4 = (size_t)n * (PER_N / 4) + t3 * PER_T4;  // f4 offset
    const float4* T4 = reinterpret_cast<const float4*>(T) + t3 * PER_T4;
    float4* rt4 = reinterpret_cast<float4*>(out_rt) + base4;
    float4* tp4 = reinterpret_cast<float4*>(out_tp) + base4;

    // ---- Phase A: rightmost_term only (single contiguous write stream) ----
    {
        int m    = tid % 5;        // c2 block = 4*m
        int la   = tid / 100;      // local row [0,10)
        int r100 = tid % 100;

        #pragma unroll
        for (int k = 0; k < NITER; ++k) {
            const int  i   = tid + k * NTHREADS;
            const bool act = (k < NITER - 1) || (tid < TAIL);
            if (act) {
                const float4 t  = __ldg(&T4[i]);
                const float4 sv = *reinterpret_cast<const float4*>(
                                      s_stats + la * C2VAL + 4 * m);
                const float inv = s_inv[la];
                float4 r;
                r.x = t.x * sv.x * inv;  r.y = t.y * sv.y * inv;
                r.z = t.z * sv.z * inv;  r.w = t.w * sv.w * inv;
                __stcs(&rt4[i], r);
            }
            const bool wrap = (m == 4);
            m = wrap ? 0 : m + 1;
            la += 2; r100 += 56;
            if (r100 >= 100) { la += 1; r100 -= 100; }
        }
    }

    // ---- Phase B: transition_posterior + p_Q (single contiguous stream) ----
    {
        int m    = tid % 5;
        int c    = (tid / 5) % CVAL;
        int la   = tid / 100;
        int r100 = tid % 100;

        #pragma unroll
        for (int k = 0; k < NITER; ++k) {
            const int  i   = tid + k * NTHREADS;
            const bool act = (k < NITER - 1) || (tid < TAIL);

            float v = 0.0f;
            if (act) {
                const float4 t  = __ldg(&T4[i]);   // L1 hit (loaded in phase A)
                const float4 sv = *reinterpret_cast<const float4*>(
                                      s_stats + la * C2VAL + 4 * m);
                const float wi = s_inv[la] * s_w[la];
                float4 p;
                p.x = t.x * sv.x * wi;  p.y = t.y * sv.y * wi;
                p.z = t.z * sv.z * wi;  p.w = t.w * sv.w * wi;
                __stcs(&tp4[i], p);
                v = (p.x + p.y) + (p.z + p.w);
            }

            // segmented reduction over runs of 5 equal-c lanes (d = 1,2,4)
            float o;
            o = __shfl_down_sync(0xFFFFFFFFu, v, 1);
            if (m <= 3 && lane < 31) v += o;
            o = __shfl_down_sync(0xFFFFFFFFu, v, 2);
            if (m <= 2 && lane < 30) v += o;
            o = __shfl_down_sync(0xFFFFFFFFu, v, 4);
            if (m == 0 && lane < 28) v += o;

            // head lanes have distinct c within a warp-iter -> plain RMW safe
            if (m == 0 || lane == 0) s_pqw[warp][c] += v;

            const bool wrap = (m == 4);
            m = wrap ? 0 : m + 1;
            c += wrap ? 12 : 11;
            if (c >= CVAL) c -= CVAL;
            la += 2; r100 += 56;
            if (r100 >= 100) { la += 1; r100 -= 100; }
        }
    }

    __syncthreads();

    // ---- Epilogue: this tile's p_Q partial -> global accumulate ----
    if (tid < CVAL) {
        float s = 0.0f;
        #pragma unroll
        for (int w8 = 0; w8 < NWARPS; ++w8) s += s_pqw[w8][tid];
        atomicAdd(&out_pq[(size_t)n * CVAL + tid], s);   // 3 adds per (n,c)
    }
}

extern "C" void kernel_launch(void* const* d_in, const int* in_sizes, int n_in,
                              void* d_out, int out_size)
{
    const float* stats  = (const float*)d_in[0];  // [N, L, A, C2]
    const float* layerS = (const float*)d_in[1];  // [L]
    const float* arcS   = (const float*)d_in[2];  // [L, A]
    const float* T      = (const float*)d_in[3];  // [L, A, C, C2]

    const int N = in_sizes[0] / KDIM;

    float* out    = (float*)d_out;
    float* out_pq = out;
    float* out_tp = out_pq + (size_t)N * CVAL;
    float* out_rt = out_tp + (size_t)N * PER_N;

    const int pq_total = N * CVAL;
    zero_pq_kernel<<<(pq_total + NTHREADS - 1) / NTHREADS, NTHREADS>>>(
        out_pq, pq_total);
    cgmm_kernel<<<3 * N, NTHREADS>>>(stats, layerS, arcS, T,
                                     out_pq, out_tp, out_rt);
}

// round 16
// speedup vs baseline: 1.5257x; 1.5257x over previous
#include <cuda_runtime.h>

// CGMMTransition: N=10000, L=5, A=6, C=20, C2=20
// R13 structure (third-n blocks, grid 30000), single variable changed:
// DEFAULT cache policy stores (L2 write-combining) instead of __stcs.
// Outputs (concatenated in d_out, fp32):
//   p_Q_given_obs        [N, C]           at offset 0
//   transition_posterior [N, L, A, C, C2] at offset N*C
//   rightmost_term       [N, L, A, C, C2] at offset N*C + N*L*A*C*C2

#define LVAL   5
#define AVAL   6
#define CVAL   20
#define C2VAL  20
#define LA     30      // L*A
#define LAT    10      // la rows per tile (third of an n)
#define KDIM   600     // LA*C2
#define KDIMT  200     // stats floats per tile
#define PER_N  12000   // LA*C*C2
#define PER_T4 1000    // float4s per tile
#define NTHREADS 256
#define NWARPS 8
#define NITER  4       // ceil(1000/256); iter 3 partial (tid < 232)
#define TAIL   (PER_T4 - 3 * NTHREADS)    // 232

__global__ void zero_pq_kernel(float* __restrict__ out_pq, int total)
{
    int i = blockIdx.x * blockDim.x + threadIdx.x;
    if (i < total) out_pq[i] = 0.0f;
}

__global__ void __launch_bounds__(NTHREADS, 8)
cgmm_kernel(const float* __restrict__ stats,
            const float* __restrict__ layerS,
            const float* __restrict__ arcS,
            const float* __restrict__ T,
            float* __restrict__ out_pq,
            float* __restrict__ out_tp,
            float* __restrict__ out_rt)
{
    __shared__ float s_stats[KDIMT];          // this tile's 10 rows
    __shared__ float s_inv[LAT];
    __shared__ float s_w[LAT];
    __shared__ float s_pqw[NWARPS][CVAL];     // per-warp c-bins (non-atomic)

    const int tid  = threadIdx.x;
    const int warp = tid >> 5;
    const int lane = tid & 31;

    const int n   = blockIdx.x / 3;
    const int t3  = blockIdx.x - 3 * n;        // tile index 0..2
    const int la0 = t3 * LAT;                  // global la base for this tile

    // ---- Phase 0: stage this tile's stats (50 float4s; guard < 256 OK) ----
    const float4* g_stats4 = reinterpret_cast<const float4*>(
        stats + (size_t)n * KDIM + la0 * C2VAL);   // byte off 800*t3: aligned
    if (tid < KDIMT / 4) {
        float4 v = __ldcs(&g_stats4[tid]);    // streamed: read exactly once
        reinterpret_cast<float4*>(s_stats)[tid] = v;
    }
    if (tid < NWARPS * CVAL)                   // 160 < 256 OK
        reinterpret_cast<float*>(s_pqw)[tid] = 0.0f;
    if (tid < LAT)                             // 10 < 256 OK
        s_w[tid] = layerS[(la0 + tid) / AVAL] * arcS[la0 + tid];
    __syncthreads();

    // ---- Phase 1: inverse row-sums (10 rows; guard < 256 OK) ----
    if (tid < LAT) {
        float s = 0.0f;
        #pragma unroll
        for (int j = 0; j < C2VAL; ++j) s += s_stats[tid * C2VAL + j];
        s_inv[tid] = (s == 0.0f) ? 1.0f : 1.0f / s;
    }
    __syncthreads();

    // ---- Phase 2: elementwise stream over this tile's 1000 float4s ----
    const size_t base4 = (size_t)n * (PER_N / 4) + t3 * PER_T4;  // f4 offset
    const float4* T4 = reinterpret_cast<const float4*>(T) + t3 * PER_T4;
    float4* rt4 = reinterpret_cast<float4*>(out_rt) + base4;
    float4* tp4 = reinterpret_cast<float4*>(out_tp) + base4;

    // division-free index state for local i = tid + 256*k (element e = 4*i):
    //   m = i%5 (c2 block = 4m), c = (i/5)%20, la = i/100 in [0,10)
    int m    = tid % 5;
    int c    = (tid / 5) % CVAL;
    int la   = tid / 100;
    int r100 = tid % 100;

    #pragma unroll
    for (int k = 0; k < NITER; ++k) {
        const int  i   = tid + k * NTHREADS;
        const bool act = (k < NITER - 1) || (tid < TAIL);

        float v = 0.0f;
        if (act) {
            const float4 t  = __ldg(&T4[i]);   // L1-resident, coalesced
            const float4 sv = *reinterpret_cast<const float4*>(
                                  s_stats + la * C2VAL + 4 * m);
            const float inv = s_inv[la];
            const float w   = s_w[la];
            float4 r, p;
            r.x = t.x * sv.x * inv;  r.y = t.y * sv.y * inv;
            r.z = t.z * sv.z * inv;  r.w = t.w * sv.w * inv;
            p.x = r.x * w;  p.y = r.y * w;  p.z = r.z * w;  p.w = r.w * w;
            rt4[i] = r;     // DEFAULT policy: L2 write-combining (vs __stcs)
            tp4[i] = p;
            v = (p.x + p.y) + (p.z + p.w);
        }

        // segmented reduction over runs of 5 equal-c lanes (d = 1,2,4)
        float o;
        o = __shfl_down_sync(0xFFFFFFFFu, v, 1);
        if (m <= 3 && lane < 31) v += o;
        o = __shfl_down_sync(0xFFFFFFFFu, v, 2);
        if (m <= 2 && lane < 30) v += o;
        o = __shfl_down_sync(0xFFFFFFFFu, v, 4);
        if (m == 0 && lane < 28) v += o;

        // head lanes have distinct c within a warp-iter -> plain RMW safe
        if (m == 0 || lane == 0) s_pqw[warp][c] += v;

        const bool wrap = (m == 4);
        m = wrap ? 0 : m + 1;
        c += wrap ? 12 : 11;
        if (c >= CVAL) c -= CVAL;
        la += 2; r100 += 56;
        if (r100 >= 100) { la += 1; r100 -= 100; }
    }

    __syncthreads();

    // ---- Epilogue: this tile's p_Q partial -> global accumulate ----
    if (tid < CVAL) {
        float s = 0.0f;
        #pragma unroll
        for (int w8 = 0; w8 < NWARPS; ++w8) s += s_pqw[w8][tid];
        atomicAdd(&out_pq[(size_t)n * CVAL + tid], s);   // 3 adds per (n,c)
    }
}

extern "C" void kernel_launch(void* const* d_in, const int* in_sizes, int n_in,
                              void* d_out, int out_size)
{
    const float* stats  = (const float*)d_in[0];  // [N, L, A, C2]
    const float* layerS = (const float*)d_in[1];  // [L]
    const float* arcS   = (const float*)d_in[2];  // [L, A]
    const float* T      = (const float*)d_in[3];  // [L, A, C, C2]

    const int N = in_sizes[0] / KDIM;

    float* out    = (float*)d_out;
    float* out_pq = out;
    float* out_tp = out_pq + (size_t)N * CVAL;
    float* out_rt = out_tp + (size_t)N * PER_N;

    const int pq_total = N * CVAL;
    zero_pq_kernel<<<(pq_total + NTHREADS - 1) / NTHREADS, NTHREADS>>>(
        out_pq, pq_total);
    cgmm_kernel<<<3 * N, NTHREADS>>>(stats, layerS, arcS, T,
                                     out_pq, out_tp, out_rt);
}